// round 1
// baseline (speedup 1.0000x reference)
#include <cuda_runtime.h>

#define Sdim 2048
#define Bdim 2
#define Edim 1024
#define Hn   16
#define HDdim 64
#define Mrows (Sdim*Bdim)   // 4096 token rows

// Scratch (device globals: allocation-free per harness rules)
__device__ float g_Q[(size_t)Bdim*Hn*Sdim*HDdim];   // [b*H+h][s][d]
__device__ float g_K[(size_t)Bdim*Hn*Sdim*HDdim];
__device__ float g_V[(size_t)Bdim*Hn*Sdim*HDdim];
__device__ float g_ctx[(size_t)Mrows*Edim];         // [s*B+b][E]

// C[M,N] = X[M,K] @ W[N,K]^T + bias, K = N = E. 64x64 tile, 256 threads, 4x4/thread.
// DEST 0/1/2: scatter into g_Q/g_K/g_V head-major. DEST 3: read g_ctx, write plain out.
template<int DEST>
__global__ __launch_bounds__(256) void gemm_nt_bias(
        const float* __restrict__ X, const float* __restrict__ W,
        const float* __restrict__ bias, float* __restrict__ out) {
    __shared__ float As[64][17];
    __shared__ float Bs[64][17];
    const int tid = threadIdx.x;
    const int tx = tid & 15, ty = tid >> 4;
    const int m0 = blockIdx.y << 6, n0 = blockIdx.x << 6;
    const int lr = tid >> 2;          // 0..63
    const int lc = (tid & 3) << 2;    // 0,4,8,12
    const float* Xp = (DEST == 3) ? (const float*)g_ctx : X;

    float acc[4][4] = {};
    const float* xrow = Xp + (size_t)(m0 + lr) * Edim + lc;
    const float* wrow = W  + (size_t)(n0 + lr) * Edim + lc;

    for (int k0 = 0; k0 < Edim; k0 += 16) {
        float4 a = *(const float4*)(xrow + k0);
        float4 b = *(const float4*)(wrow + k0);
        As[lr][lc+0]=a.x; As[lr][lc+1]=a.y; As[lr][lc+2]=a.z; As[lr][lc+3]=a.w;
        Bs[lr][lc+0]=b.x; Bs[lr][lc+1]=b.y; Bs[lr][lc+2]=b.z; Bs[lr][lc+3]=b.w;
        __syncthreads();
#pragma unroll
        for (int kk = 0; kk < 16; kk++) {
            float av[4], bv[4];
#pragma unroll
            for (int i = 0; i < 4; i++) av[i] = As[(ty<<2)+i][kk];
#pragma unroll
            for (int j = 0; j < 4; j++) bv[j] = Bs[(tx<<2)+j][kk];
#pragma unroll
            for (int i = 0; i < 4; i++)
#pragma unroll
                for (int j = 0; j < 4; j++)
                    acc[i][j] = fmaf(av[i], bv[j], acc[i][j]);
        }
        __syncthreads();
    }

    const int nb = n0 + (tx<<2);
#pragma unroll
    for (int i = 0; i < 4; i++) {
        const int m = m0 + (ty<<2) + i;
        float4 r;
        r.x = acc[i][0] + bias[nb+0];
        r.y = acc[i][1] + bias[nb+1];
        r.z = acc[i][2] + bias[nb+2];
        r.w = acc[i][3] + bias[nb+3];
        if (DEST == 3) {
            *(float4*)(out + (size_t)m * Edim + nb) = r;
        } else {
            const int s = m >> 1, b = m & 1;        // m = s*B + b (B=2)
            const int h = nb >> 6, d = nb & 63;     // n-tile == one head
            float* dst = (DEST == 0) ? g_Q : (DEST == 1) ? g_K : g_V;
            *(float4*)(dst + ((size_t)(b*Hn + h) * Sdim + s) * HDdim + d) = r;
        }
    }
}

// Flash attention, fp32, unscaled scores (faithful to reference).
// Block = (qtile of 64 rows, one bh). 256 threads as 16x16; scores thread-tile 4x2,
// output thread-tile 4x4. BLOCK_N = 32 keys/iter.
__global__ __launch_bounds__(256) void flash_attn_kernel() {
    __shared__ float Qs[64][65];
    __shared__ float Ks[32][65];
    __shared__ float Vs[32][64];
    __shared__ float Ps[64][33];

    const int tid = threadIdx.x;
    const int tx = tid & 15, ty = tid >> 4;
    const int bh = blockIdx.y;            // b*H + h
    const int q0 = blockIdx.x << 6;

    const float* Qp = g_Q + ((size_t)bh * Sdim + q0) * HDdim;
    const float* Kp = g_K + (size_t)bh * Sdim * HDdim;
    const float* Vp = g_V + (size_t)bh * Sdim * HDdim;

    // Load Q tile 64x64 (1024 float4, 4/thread)
    for (int i = tid; i < 64*16; i += 256) {
        const int r = i >> 4, c = (i & 15) << 2;
        float4 v = *(const float4*)(Qp + r*HDdim + c);
        Qs[r][c+0]=v.x; Qs[r][c+1]=v.y; Qs[r][c+2]=v.z; Qs[r][c+3]=v.w;
    }

    float acc[4][4] = {};
    float mrow[4] = {-1e30f,-1e30f,-1e30f,-1e30f};
    float lrow[4] = {0.f,0.f,0.f,0.f};

    for (int kt = 0; kt < Sdim/32; kt++) {
        // Load K and V tiles 32x64 (512 float4 each, 2/thread each)
        for (int i = tid; i < 32*16; i += 256) {
            const int r = i >> 4, c = (i & 15) << 2;
            float4 kv = *(const float4*)(Kp + (size_t)(kt*32 + r)*HDdim + c);
            Ks[r][c+0]=kv.x; Ks[r][c+1]=kv.y; Ks[r][c+2]=kv.z; Ks[r][c+3]=kv.w;
            float4 vv = *(const float4*)(Vp + (size_t)(kt*32 + r)*HDdim + c);
            Vs[r][c+0]=vv.x; Vs[r][c+1]=vv.y; Vs[r][c+2]=vv.z; Vs[r][c+3]=vv.w;
        }
        __syncthreads();

        // S = Q @ K^T  (64x32), thread owns rows ty*4+i, cols tx*2+j
        float s[4][2] = {};
#pragma unroll
        for (int kk = 0; kk < 64; kk++) {
            float av[4], bv[2];
#pragma unroll
            for (int i = 0; i < 4; i++) av[i] = Qs[(ty<<2)+i][kk];
#pragma unroll
            for (int j = 0; j < 2; j++) bv[j] = Ks[(tx<<1)+j][kk];
#pragma unroll
            for (int i = 0; i < 4; i++) {
                s[i][0] = fmaf(av[i], bv[0], s[i][0]);
                s[i][1] = fmaf(av[i], bv[1], s[i][1]);
            }
        }

        // Online softmax (row groups = 16 consecutive lanes, same ty)
#pragma unroll
        for (int i = 0; i < 4; i++) {
            float mx = fmaxf(s[i][0], s[i][1]);
#pragma unroll
            for (int off = 8; off >= 1; off >>= 1)
                mx = fmaxf(mx, __shfl_xor_sync(0xffffffffu, mx, off, 16));
            const float mnew = fmaxf(mrow[i], mx);
            const float p0 = __expf(s[i][0] - mnew);
            const float p1 = __expf(s[i][1] - mnew);
            float rs = p0 + p1;
#pragma unroll
            for (int off = 8; off >= 1; off >>= 1)
                rs += __shfl_xor_sync(0xffffffffu, rs, off, 16);
            const float alpha = __expf(mrow[i] - mnew);
            lrow[i] = lrow[i] * alpha + rs;
            mrow[i] = mnew;
#pragma unroll
            for (int j = 0; j < 4; j++) acc[i][j] *= alpha;
            Ps[(ty<<2)+i][(tx<<1)+0] = p0;
            Ps[(ty<<2)+i][(tx<<1)+1] = p1;
        }
        __syncthreads();

        // O += P @ V  (64x64), thread owns rows ty*4+i, cols tx*4..+3
#pragma unroll
        for (int c = 0; c < 32; c++) {
            const float4 v = *(const float4*)&Vs[c][tx<<2];
#pragma unroll
            for (int i = 0; i < 4; i++) {
                const float p = Ps[(ty<<2)+i][c];
                acc[i][0] = fmaf(p, v.x, acc[i][0]);
                acc[i][1] = fmaf(p, v.y, acc[i][1]);
                acc[i][2] = fmaf(p, v.z, acc[i][2]);
                acc[i][3] = fmaf(p, v.w, acc[i][3]);
            }
        }
        __syncthreads();
    }

    // Epilogue: normalize and write to ctx [s*B+b][h*HD+d]
    const int b = bh >> 4, h = bh & 15;
#pragma unroll
    for (int i = 0; i < 4; i++) {
        const float inv = 1.0f / lrow[i];
        const int sg = q0 + (ty<<2) + i;
        float4 r;
        r.x = acc[i][0]*inv; r.y = acc[i][1]*inv;
        r.z = acc[i][2]*inv; r.w = acc[i][3]*inv;
        *(float4*)(g_ctx + ((size_t)sg * Bdim + b) * Edim + h*HDdim + (tx<<2)) = r;
    }
}

extern "C" void kernel_launch(void* const* d_in, const int* in_sizes, int n_in,
                              void* d_out, int out_size) {
    const float* query = (const float*)d_in[0];
    const float* key_  = (const float*)d_in[1];
    const float* value = (const float*)d_in[2];
    const float* Wq = (const float*)d_in[3];
    const float* bq = (const float*)d_in[4];
    const float* Wk = (const float*)d_in[5];
    const float* bk = (const float*)d_in[6];
    const float* Wv = (const float*)d_in[7];
    const float* bv = (const float*)d_in[8];
    const float* Wo = (const float*)d_in[9];
    const float* bo = (const float*)d_in[10];
    float* out = (float*)d_out;

    dim3 gproj(Edim/64, Mrows/64);   // 16 x 64
    gemm_nt_bias<0><<<gproj, 256>>>(query, Wq, bq, nullptr);
    gemm_nt_bias<1><<<gproj, 256>>>(key_,  Wk, bk, nullptr);
    gemm_nt_bias<2><<<gproj, 256>>>(value, Wv, bv, nullptr);

    flash_attn_kernel<<<dim3(Sdim/64, Bdim*Hn), 256>>>();

    gemm_nt_bias<3><<<gproj, 256>>>(nullptr, Wo, bo, out);
}